// round 4
// baseline (speedup 1.0000x reference)
#include <cuda_runtime.h>
#include <cstdint>
#include <cstddef>

// GCL (EGNN-style), factorized + tf32 mma.sync.
// Edge kernel is warp-specialized: 4 producer warps gather/silu into a
// double-buffered SMEM tile while 8 consumer warps do MMA + epilogue,
// synchronized with named barriers. Epilogue uses float4 STG + vector RED.
// Output: [h_out (N*D) | mij (E*D)] fp32.

#define DD    128
#define PAD   132     // ts row pitch (floats)
#define PADW  136     // ws row pitch (floats)
#define TM    128
#define NTHR  256     // pre/node block
#define ETHR  384     // edge block: 256 consumers + 128 producers
#define MAXN  50048
#define EGRID 148

// named barrier ids (count = ETHR)
#define BAR_FULL0  1
#define BAR_FULL1  2
#define BAR_EMPTY0 3
#define BAR_EMPTY1 4

__device__ float g_A[(size_t)MAXN * DD];
__device__ float g_B[(size_t)MAXN * DD];
__device__ float g_C[(size_t)MAXN * DD];
__device__ float g_agg[(size_t)MAXN * DD];
__device__ int   g_is64;

__device__ __forceinline__ float silu_f(float x) { return x / (1.0f + __expf(-x)); }

__device__ __forceinline__ float to_tf32(float x) {
    uint32_t u;
    asm("cvt.rna.tf32.f32 %0, %1;" : "=r"(u) : "f"(x));
    return __uint_as_float(u);
}

__device__ __forceinline__ void mma_tf32(float c[4], uint32_t a0, uint32_t a1,
                                         uint32_t a2, uint32_t a3,
                                         uint32_t b0, uint32_t b1) {
    asm("mma.sync.aligned.m16n8k8.row.col.f32.tf32.tf32.f32 "
        "{%0,%1,%2,%3}, {%4,%5,%6,%7}, {%8,%9}, {%0,%1,%2,%3};"
        : "+f"(c[0]), "+f"(c[1]), "+f"(c[2]), "+f"(c[3])
        : "r"(a0), "r"(a1), "r"(a2), "r"(a3), "r"(b0), "r"(b1));
}

__device__ __forceinline__ void red_add_v4(float* gaddr, float4 v) {
    asm volatile("red.global.add.v4.f32 [%0], {%1,%2,%3,%4};"
                 :: "l"(gaddr), "f"(v.x), "f"(v.y), "f"(v.z), "f"(v.w)
                 : "memory");
}

#define NBAR_SYNC(id)   asm volatile("bar.sync %0, %1;"   :: "r"(id), "r"(ETHR) : "memory")
#define NBAR_ARRIVE(id) asm volatile("bar.arrive %0, %1;" :: "r"(id), "r"(ETHR) : "memory")

// Load 128x128 row-major W into ws[k*PADW + n], tf32-rounded. 256 threads.
__device__ __forceinline__ void load_w(float* ws, const float* __restrict__ W, int tid) {
    #pragma unroll
    for (int i = 0; i < 16; i++) {
        int idx = tid + i * 256;           // float4 index, 4096 total
        int k = idx >> 5;
        int n4 = (idx & 31) << 2;
        float4 v = __ldg((const float4*)W + idx);
        v.x = to_tf32(v.x); v.y = to_tf32(v.y);
        v.z = to_tf32(v.z); v.w = to_tf32(v.w);
        *(float4*)(ws + k * PADW + n4) = v;
    }
}

// 128x128x128 warp-tiled MMA: acc += ts[128][k] @ ws[k][n].
// 8 warps, grid 2(M)x4(N), warp tile M64xN32, m16n8k8 tf32.
__device__ __forceinline__ void warp_gemm(const float* __restrict__ ts,
                                          const float* __restrict__ ws,
                                          float acc[4][4][4],
                                          int wm, int wn, int g, int tg) {
    const float* ta = ts + (wm * 64 + g) * PAD + tg;
    const float* wb = ws + tg * PADW + wn * 32 + g;
    #pragma unroll
    for (int ks = 0; ks < 16; ks++) {
        int kb = ks * 8;
        uint32_t a[4][4];
        #pragma unroll
        for (int mt = 0; mt < 4; mt++) {
            const float* p = ta + mt * 16 * PAD + kb;
            a[mt][0] = __float_as_uint(p[0]);
            a[mt][1] = __float_as_uint(p[8 * PAD]);
            a[mt][2] = __float_as_uint(p[4]);
            a[mt][3] = __float_as_uint(p[8 * PAD + 4]);
        }
        #pragma unroll
        for (int nt = 0; nt < 4; nt++) {
            const float* q = wb + kb * PADW + nt * 8;
            uint32_t b0 = __float_as_uint(q[0]);
            uint32_t b1 = __float_as_uint(q[4 * PADW]);
            #pragma unroll
            for (int mt = 0; mt < 4; mt++)
                mma_tf32(acc[mt][nt], a[mt][0], a[mt][1], a[mt][2], a[mt][3], b0, b1);
        }
    }
}

// ============================ setup ============================

__global__ void zero_detect_kernel(const void* __restrict__ eidx) {
    size_t i = (size_t)blockIdx.x * blockDim.x + threadIdx.x;
    size_t n4 = (size_t)MAXN * DD / 4;
    if (i < n4) ((float4*)g_agg)[i] = make_float4(0.f, 0.f, 0.f, 0.f);
    if (blockIdx.x == 0 && threadIdx.x == 0) {
        const unsigned* p = (const unsigned*)eidx;
        int is64 = 1;
        for (int k = 0; k < 64; k++)
            if (p[2 * k + 1] != 0u) { is64 = 0; break; }
        g_is64 = is64;
    }
}

// ============================ pre: A, B, C ============================

__global__ void __launch_bounds__(NTHR, 1)
pre_kernel(const float* __restrict__ h, const float* __restrict__ We1,
           const float* __restrict__ Wn1, const float* __restrict__ bn1, int Nn) {
    extern __shared__ float sm[];
    float* ts = sm;
    float* ws = sm + TM * PAD;
    int tid = threadIdx.x, lane = tid & 31, wid = tid >> 5;
    int wm = wid >> 2, wn = wid & 3, g = lane >> 2, tg = lane & 3;
    int nb = blockIdx.x * TM;
    int el = tid >> 1, half = tid & 1;

    {
        int node = nb + el;
        float* td = ts + el * PAD + half * 64;
        if (node < Nn) {
            const float4* h4 = (const float4*)(h + (size_t)node * DD + half * 64);
            #pragma unroll
            for (int i = 0; i < 16; i++) {
                float4 v = h4[i];
                v.x = to_tf32(v.x); v.y = to_tf32(v.y);
                v.z = to_tf32(v.z); v.w = to_tf32(v.w);
                ((float4*)td)[i] = v;
            }
        } else {
            float4 z = make_float4(0.f, 0.f, 0.f, 0.f);
            #pragma unroll
            for (int i = 0; i < 16; i++) ((float4*)td)[i] = z;
        }
    }

    for (int ph = 0; ph < 3; ph++) {
        const float* W = (ph == 0) ? We1 : (ph == 1) ? (We1 + DD * DD) : Wn1;
        __syncthreads();
        load_w(ws, W, tid);
        __syncthreads();

        float acc[4][4][4] = {};
        warp_gemm(ts, ws, acc, wm, wn, g, tg);

        float* out = (ph == 0) ? g_A : (ph == 1) ? g_B : g_C;
        #pragma unroll
        for (int mt = 0; mt < 4; mt++) {
            int r0 = wm * 64 + mt * 16 + g;
            int n0 = nb + r0, n1 = n0 + 8;
            #pragma unroll
            for (int nt = 0; nt < 4; nt++) {
                int cb = wn * 32 + nt * 8 + tg * 2;
                float2 bb = make_float2(0.f, 0.f);
                if (ph == 2) bb = *(const float2*)(bn1 + cb);
                if (n0 < Nn)
                    *(float2*)(out + (size_t)n0 * DD + cb) =
                        make_float2(acc[mt][nt][0] + bb.x, acc[mt][nt][1] + bb.y);
                if (n1 < Nn)
                    *(float2*)(out + (size_t)n1 * DD + cb) =
                        make_float2(acc[mt][nt][2] + bb.x, acc[mt][nt][3] + bb.y);
            }
        }
    }
}

// ============================ edge (warp-specialized, persistent) ============================
// SMEM: ts0 [128*PAD] | ts1 [128*PAD] | ws [128*PADW]   (204,800 B dynamic)

__global__ void __launch_bounds__(ETHR, 1)
edge_kernel(const void* __restrict__ eidx, const float* __restrict__ be1,
            const float* __restrict__ We2, const float* __restrict__ be2,
            float* __restrict__ mij, int Ee) {
    extern __shared__ float sm[];
    float* ts0 = sm;
    float* ts1 = sm + TM * PAD;
    float* ws  = sm + 2 * TM * PAD;
    __shared__ int rsh[2][TM];
    __shared__ alignas(16) float sbe1[DD];
    __shared__ alignas(16) float sbe2[DD];

    int tid = threadIdx.x;
    if (tid < DD) sbe1[tid] = be1[tid];
    else if (tid < 2 * DD) sbe2[tid - DD] = be2[tid - DD];
    int is64 = g_is64;
    __syncthreads();                        // sbe1/sbe2 visible to all roles

    int ntiles = (Ee + TM - 1) >> 7;

    if (tid < 256) {
        // ---------------- consumers: 8 warps, MMA + epilogue ----------------
        int lane = tid & 31, wid = tid >> 5;
        int wm = wid >> 2, wn = wid & 3, g = lane >> 2, tg = lane & 3;
        int evenlane = (tg & 1) == 0;

        load_w(ws, We2, tid);               // all consumers finish before FULL0 sync

        int it = 0;
        for (int t = blockIdx.x; t < ntiles; t += gridDim.x, it++) {
            int buf = it & 1;
            NBAR_SYNC(buf ? BAR_FULL1 : BAR_FULL0);   // ts[buf]+rsh[buf] ready (also orders load_w)

            const float* ts = buf ? ts1 : ts0;
            float acc[4][4][4] = {};
            warp_gemm(ts, ws, acc, wm, wn, g, tg);

            #pragma unroll
            for (int mt = 0; mt < 4; mt++) {
                int r0 = wm * 64 + mt * 16 + g;
                int e0 = t * TM + r0, e1 = e0 + 8;
                int rr0 = rsh[buf][r0], rr1 = rsh[buf][r0 + 8];
                #pragma unroll
                for (int nt = 0; nt < 4; nt++) {
                    int cb2 = wn * 32 + nt * 8 + tg * 2;
                    float2 u0 = make_float2(silu_f(acc[mt][nt][0] + sbe2[cb2]),
                                            silu_f(acc[mt][nt][1] + sbe2[cb2 + 1]));
                    float2 u1 = make_float2(silu_f(acc[mt][nt][2] + sbe2[cb2]),
                                            silu_f(acc[mt][nt][3] + sbe2[cb2 + 1]));
                    // lane-pair merge: even lane -> row g float4, odd -> row g+8
                    float sx = evenlane ? u1.x : u0.x;
                    float sy = evenlane ? u1.y : u0.y;
                    float rx = __shfl_xor_sync(0xffffffffu, sx, 1);
                    float ry = __shfl_xor_sync(0xffffffffu, sy, 1);
                    int c4 = wn * 32 + nt * 8 + (tg & 2) * 2;
                    if (evenlane) {
                        if (e0 < Ee) {
                            float4 v = make_float4(u0.x, u0.y, rx, ry);
                            *(float4*)(mij + (size_t)e0 * DD + c4) = v;
                            red_add_v4(g_agg + (size_t)rr0 * DD + c4, v);
                        }
                    } else {
                        if (e1 < Ee) {
                            float4 v = make_float4(rx, ry, u1.x, u1.y);
                            *(float4*)(mij + (size_t)e1 * DD + c4) = v;
                            red_add_v4(g_agg + (size_t)rr1 * DD + c4, v);
                        }
                    }
                }
            }
            NBAR_ARRIVE(buf ? BAR_EMPTY1 : BAR_EMPTY0);
        }
    } else {
        // ---------------- producers: 4 warps, gather -> silu -> SMEM ----------------
        int pid = tid - 256;                // 0..127, one edge row each
        int it = 0;
        for (int t = blockIdx.x; t < ntiles; t += gridDim.x, it++) {
            int buf = it & 1;
            if (it >= 2) NBAR_SYNC(buf ? BAR_EMPTY1 : BAR_EMPTY0);

            int e = t * TM + pid;
            int ec = (e < Ee) ? e : (Ee - 1);
            int r, c;
            if (is64) {
                const long long* p = (const long long*)eidx;
                r = (int)p[ec];
                c = (int)p[(size_t)Ee + ec];
            } else {
                const int* p = (const int*)eidx;
                r = p[ec];
                c = p[Ee + ec];
            }
            rsh[buf][pid] = r;
            const float4* Ar = (const float4*)(g_A + (size_t)r * DD);
            const float4* Br = (const float4*)(g_B + (size_t)c * DD);
            const float4* bb = (const float4*)sbe1;
            float4* td = (float4*)((buf ? ts1 : ts0) + pid * PAD);
            #pragma unroll 8
            for (int i = 0; i < 32; i++) {
                float4 a = Ar[i], b = Br[i], e1v = bb[i];
                float4 v;
                v.x = to_tf32(silu_f(a.x + b.x + e1v.x));
                v.y = to_tf32(silu_f(a.y + b.y + e1v.y));
                v.z = to_tf32(silu_f(a.z + b.z + e1v.z));
                v.w = to_tf32(silu_f(a.w + b.w + e1v.w));
                td[i] = v;
            }
            NBAR_ARRIVE(buf ? BAR_FULL1 : BAR_FULL0);
        }
    }
}

// ============================ node ============================

__global__ void __launch_bounds__(NTHR, 1)
node_kernel(const float* __restrict__ h, const float* __restrict__ Wn1,
            const float* __restrict__ Wn2, const float* __restrict__ bn2,
            float* __restrict__ hout, int Nn) {
    extern __shared__ float sm[];
    float* ts = sm;
    float* ws = sm + TM * PAD;
    int tid = threadIdx.x, lane = tid & 31, wid = tid >> 5;
    int wm = wid >> 2, wn = wid & 3, g = lane >> 2, tg = lane & 3;
    int nb = blockIdx.x * TM;
    int el = tid >> 1, half = tid & 1;

    {
        int node = nb + el;
        float* td = ts + el * PAD + half * 64;
        if (node < Nn) {
            const float4* g4 = (const float4*)(g_agg + (size_t)node * DD + half * 64);
            #pragma unroll
            for (int i = 0; i < 16; i++) {
                float4 v = g4[i];
                v.x = to_tf32(v.x * 0.01f); v.y = to_tf32(v.y * 0.01f);
                v.z = to_tf32(v.z * 0.01f); v.w = to_tf32(v.w * 0.01f);
                ((float4*)td)[i] = v;
            }
        } else {
            float4 z = make_float4(0.f, 0.f, 0.f, 0.f);
            #pragma unroll
            for (int i = 0; i < 16; i++) ((float4*)td)[i] = z;
        }
    }
    load_w(ws, Wn1 + DD * DD, tid);        // Wn1_bot
    __syncthreads();

    float acc[4][4][4] = {};
    warp_gemm(ts, ws, acc, wm, wn, g, tg);
    __syncthreads();

    #pragma unroll
    for (int mt = 0; mt < 4; mt++) {
        int r0 = wm * 64 + mt * 16 + g;
        int n0 = nb + r0, n1 = n0 + 8;
        #pragma unroll
        for (int nt = 0; nt < 4; nt++) {
            int cb = wn * 32 + nt * 8 + tg * 2;
            float2 u0 = make_float2(0.f, 0.f), u1 = u0;
            if (n0 < Nn) {
                float2 c0 = *(const float2*)(g_C + (size_t)n0 * DD + cb);
                u0 = make_float2(to_tf32(silu_f(acc[mt][nt][0] + c0.x)),
                                 to_tf32(silu_f(acc[mt][nt][1] + c0.y)));
            }
            if (n1 < Nn) {
                float2 c1 = *(const float2*)(g_C + (size_t)n1 * DD + cb);
                u1 = make_float2(to_tf32(silu_f(acc[mt][nt][2] + c1.x)),
                                 to_tf32(silu_f(acc[mt][nt][3] + c1.y)));
            }
            *(float2*)(ts + r0 * PAD + cb) = u0;
            *(float2*)(ts + (r0 + 8) * PAD + cb) = u1;
        }
    }
    load_w(ws, Wn2, tid);
    __syncthreads();

    float acc2[4][4][4] = {};
    warp_gemm(ts, ws, acc2, wm, wn, g, tg);

    #pragma unroll
    for (int mt = 0; mt < 4; mt++) {
        int r0 = wm * 64 + mt * 16 + g;
        int n0 = nb + r0, n1 = n0 + 8;
        #pragma unroll
        for (int nt = 0; nt < 4; nt++) {
            int cb = wn * 32 + nt * 8 + tg * 2;
            float2 bb = *(const float2*)(bn2 + cb);
            if (n0 < Nn) {
                float2 hv = *(const float2*)(h + (size_t)n0 * DD + cb);
                *(float2*)(hout + (size_t)n0 * DD + cb) =
                    make_float2(hv.x + acc2[mt][nt][0] + bb.x,
                                hv.y + acc2[mt][nt][1] + bb.y);
            }
            if (n1 < Nn) {
                float2 hv = *(const float2*)(h + (size_t)n1 * DD + cb);
                *(float2*)(hout + (size_t)n1 * DD + cb) =
                    make_float2(hv.x + acc2[mt][nt][2] + bb.x,
                                hv.y + acc2[mt][nt][3] + bb.y);
            }
        }
    }
}

// ============================ launcher ============================

extern "C" void kernel_launch(void* const* d_in, const int* in_sizes, int n_in,
                              void* d_out, int out_size) {
    const float* h   = (const float*)d_in[0];
    const void*  eix = d_in[1];
    const float* We1 = (const float*)d_in[2];
    const float* be1 = (const float*)d_in[3];
    const float* We2 = (const float*)d_in[4];
    const float* be2 = (const float*)d_in[5];
    const float* Wn1 = (const float*)d_in[6];
    const float* bn1 = (const float*)d_in[7];
    const float* Wn2 = (const float*)d_in[8];
    const float* bn2 = (const float*)d_in[9];

    int Nn = in_sizes[0] / DD;     // 50000
    int Ee = in_sizes[1] / 2;      // 800000

    float* hout = (float*)d_out;
    float* mij  = (float*)d_out + (size_t)Nn * DD;

    size_t smem_sim  = (size_t)(TM * PAD + DD * PADW) * sizeof(float);      // 137,216 B
    size_t smem_edge = (size_t)(2 * TM * PAD + DD * PADW) * sizeof(float);  // 204,800 B
    cudaFuncSetAttribute(pre_kernel,  cudaFuncAttributeMaxDynamicSharedMemorySize, (int)smem_sim);
    cudaFuncSetAttribute(edge_kernel, cudaFuncAttributeMaxDynamicSharedMemorySize, (int)smem_edge);
    cudaFuncSetAttribute(node_kernel, cudaFuncAttributeMaxDynamicSharedMemorySize, (int)smem_sim);

    int gz = (MAXN * DD / 4 + NTHR - 1) / NTHR;
    zero_detect_kernel<<<gz, NTHR>>>(eix);

    int gn = (Nn + TM - 1) / TM;
    pre_kernel<<<gn, NTHR, smem_sim>>>(h, We1, Wn1, bn1, Nn);

    edge_kernel<<<EGRID, ETHR, smem_edge>>>(eix, be1, We2, be2, mij, Ee);

    node_kernel<<<gn, NTHR, smem_sim>>>(h, Wn1, Wn2, bn2, hout, Nn);
}